// round 11
// baseline (speedup 1.0000x reference)
#include <cuda_runtime.h>
#include <cstdint>

using ull = unsigned long long;

// ---- all weights in one constant struct (single memcpy node) ----
struct ConstW {
    ull pWq[72];   // [e][p] = (Wq[2p][e], Wq[2p+1][e])
    ull pWk[72];
    ull pWv[72];
    ull pWo[72];
    ull pW1[144];  // [e][p] p<12
    ull pW2[144];  // [f][p] p<6
    ull pbq[6], pbk[6], pbv[6], pbo[6], pb2[6], pb1[12];
};

__constant__ ConstW cw;
__device__ ConstW gStage;

namespace {

constexpr int N = 8;
constexpr int D = 12;
constexpr int F = 24;
constexpr int V = 128;
constexpr int WARPS = 8;
constexpr int THREADS = WARPS * 32;
constexpr int ITEMS_PER_BLOCK = 32;   // 4 items per warp

#define F4C(p) (*reinterpret_cast<const float4*>(p))
#define F4(p)  (*reinterpret_cast<float4*>(p))

__device__ __forceinline__ ull pack2(float x, float y) {
    ull p; asm("mov.b64 %0, {%1, %2};" : "=l"(p) : "f"(x), "f"(y)); return p;
}
__device__ __forceinline__ void unpack2(ull p, float& x, float& y) {
    asm("mov.b64 {%0, %1}, %2;" : "=f"(x), "=f"(y) : "l"(p));
}
__device__ __forceinline__ void ffma2(ull& d, ull a, ull b) {
    asm("fma.rn.f32x2 %0, %1, %2, %0;" : "+l"(d) : "l"(a), "l"(b));
}

// ---- pack kernel: gather 12 weight buffers into pair-major staging ----
__global__ void pack_weights_kernel(
    const float* __restrict__ Wq, const float* __restrict__ bq,
    const float* __restrict__ Wk, const float* __restrict__ bk,
    const float* __restrict__ Wv, const float* __restrict__ bv,
    const float* __restrict__ Wo, const float* __restrict__ bo,
    const float* __restrict__ W1, const float* __restrict__ b1,
    const float* __restrict__ W2, const float* __restrict__ b2)
{
    const int t = threadIdx.x;
    for (int i = t; i < 72; i += 256) {
        int e = i / 6, p = i % 6;
        gStage.pWq[i] = pack2(Wq[(2*p) * D + e], Wq[(2*p+1) * D + e]);
        gStage.pWk[i] = pack2(Wk[(2*p) * D + e], Wk[(2*p+1) * D + e]);
        gStage.pWv[i] = pack2(Wv[(2*p) * D + e], Wv[(2*p+1) * D + e]);
        gStage.pWo[i] = pack2(Wo[(2*p) * D + e], Wo[(2*p+1) * D + e]);
    }
    for (int i = t; i < 144; i += 256) {
        int e = i / 12, p = i % 12;
        gStage.pW1[i] = pack2(W1[(2*p) * D + e], W1[(2*p+1) * D + e]);
    }
    for (int i = t; i < 144; i += 256) {
        int f = i / 6, p = i % 6;
        gStage.pW2[i] = pack2(W2[(2*p) * F + f], W2[(2*p+1) * F + f]);
    }
    if (t < 6) {
        gStage.pbq[t] = pack2(bq[2*t], bq[2*t+1]);
        gStage.pbk[t] = pack2(bk[2*t], bk[2*t+1]);
        gStage.pbv[t] = pack2(bv[2*t], bv[2*t+1]);
        gStage.pbo[t] = pack2(bo[2*t], bo[2*t+1]);
        gStage.pb2[t] = pack2(b2[2*t], b2[2*t+1]);
    }
    if (t < 12) gStage.pb1[t] = pack2(b1[2*t], b1[2*t+1]);
}

__global__ __launch_bounds__(THREADS, 4)
void tiny_transformer_kernel(
    const int*   __restrict__ x,
    const float* __restrict__ embed,
    const float* __restrict__ pos,
    const float* __restrict__ blm,
    float* __restrict__ out)
{
    // ---- shared: only lane-divergent data ----
    __shared__ __align__(16) float sEmbT[D * V];   // transposed [d][v] for logits
    __shared__ __align__(16) float sPos[N * D];
    __shared__ __align__(16) float sBlm[V];
    // +1 padding row so the software-pipeline over-read stays in bounds
    __shared__ __align__(16) float sXf[WARPS][4 * N * D + D];

    const int tid = threadIdx.x;

    for (int i = tid; i < D * V; i += THREADS) {
        int d = i >> 7, v = i & 127;
        sEmbT[i] = embed[v * D + d];
    }
    for (int i = tid; i < N * D; i += THREADS) sPos[i] = pos[i];
    for (int i = tid; i < V; i += THREADS) sBlm[i] = blm[i];
    __syncthreads();

    const int w    = tid >> 5;
    const int lane = tid & 31;
    const int n    = lane & 7;
    const int item_base = blockIdx.x * ITEMS_PER_BLOCK + w * 4;

    // ---- phase 1: X = embed[x] + pos (gmem gather; embed is L2/L1-hot) ----
    const int tok = __ldg(&x[item_base * N + lane]);
    float X[D];
    {
        const float4* e4 = reinterpret_cast<const float4*>(embed);
        #pragma unroll
        for (int c = 0; c < 3; c++) {
            float4 e = __ldg(&e4[tok * 3 + c]);
            float4 p = F4C(&sPos[n * D + 4 * c]);
            X[4*c+0] = e.x + p.x; X[4*c+1] = e.y + p.y;
            X[4*c+2] = e.z + p.z; X[4*c+3] = e.w + p.w;
        }
    }

    // ---- phase 2: Q,K,V (packed FFMA2 against constant port) ----
    float Qr[D], Kr[D], Vr[D];
    {
        ull q2[6], k2[6], v2[6];
        #pragma unroll
        for (int p = 0; p < 6; p++) {
            q2[p] = cw.pbq[p]; k2[p] = cw.pbk[p]; v2[p] = cw.pbv[p];
        }
        #pragma unroll
        for (int e = 0; e < D; e++) {
            const ull xp = pack2(X[e], X[e]);
            #pragma unroll
            for (int p = 0; p < 6; p++) {
                ffma2(q2[p], xp, cw.pWq[e * 6 + p]);
                ffma2(k2[p], xp, cw.pWk[e * 6 + p]);
                ffma2(v2[p], xp, cw.pWv[e * 6 + p]);
            }
        }
        #pragma unroll
        for (int p = 0; p < 6; p++) {
            unpack2(q2[p], Qr[2*p], Qr[2*p+1]);
            unpack2(k2[p], Kr[2*p], Kr[2*p+1]);
            unpack2(v2[p], Vr[2*p], Vr[2*p+1]);
        }
    }

    // ---- phase 3: scores via width-8 shuffles ----
    float S[N];
    {
        const float inv_scale = 0.28867513459481287f;  // 1/sqrt(12)
        #pragma unroll
        for (int m = 0; m < N; m++) {
            float acc = 0.f;
            #pragma unroll
            for (int e = 0; e < D; e++)
                acc += Qr[e] * __shfl_sync(0xffffffffu, Kr[e], m, 8);
            S[m] = (m <= n) ? acc * inv_scale : -1e30f;
        }
    }

    // ---- phase 4: softmax ----
    {
        float mx = S[0];
        #pragma unroll
        for (int m = 1; m < N; m++) mx = fmaxf(mx, S[m]);
        float sum = 0.f;
        #pragma unroll
        for (int m = 0; m < N; m++) { S[m] = __expf(S[m] - mx); sum += S[m]; }
        const float inv = 1.f / sum;
        #pragma unroll
        for (int m = 0; m < N; m++) S[m] *= inv;
    }

    // ---- phase 5: A = softmax @ V via shuffles ----
    float A[D];
    #pragma unroll
    for (int e = 0; e < D; e++) A[e] = 0.f;
    #pragma unroll
    for (int m = 0; m < N; m++) {
        const float s = S[m];
        #pragma unroll
        for (int e = 0; e < D; e++)
            A[e] += s * __shfl_sync(0xffffffffu, Vr[e], m, 8);
    }

    // ---- phase 6: X += A @ Wo^T + bo (packed) ----
    {
        ull o2[6];
        #pragma unroll
        for (int p = 0; p < 6; p++) o2[p] = cw.pbo[p];
        #pragma unroll
        for (int e = 0; e < D; e++) {
            const ull ap = pack2(A[e], A[e]);
            #pragma unroll
            for (int p = 0; p < 6; p++)
                ffma2(o2[p], ap, cw.pWo[e * 6 + p]);
        }
        #pragma unroll
        for (int p = 0; p < 6; p++) {
            float u, v; unpack2(o2[p], u, v);
            X[2*p] += u; X[2*p+1] += v;
        }
    }

    // ---- phase 7: H = relu(X @ W1^T + b1) (packed) ----
    float H[F];
    {
        ull h2[12];
        #pragma unroll
        for (int p = 0; p < 12; p++) h2[p] = cw.pb1[p];
        #pragma unroll
        for (int e = 0; e < D; e++) {
            const ull xp = pack2(X[e], X[e]);
            #pragma unroll
            for (int p = 0; p < 12; p++)
                ffma2(h2[p], xp, cw.pW1[e * 12 + p]);
        }
        #pragma unroll
        for (int p = 0; p < 12; p++) {
            float u, v; unpack2(h2[p], u, v);
            H[2*p]   = fmaxf(u, 0.f);
            H[2*p+1] = fmaxf(v, 0.f);
        }
    }

    // ---- phase 8: X += H @ W2^T + b2 (packed) ----
    {
        ull x2[6];
        #pragma unroll
        for (int p = 0; p < 6; p++) x2[p] = cw.pb2[p];
        #pragma unroll
        for (int f = 0; f < F; f++) {
            const ull hp = pack2(H[f], H[f]);
            #pragma unroll
            for (int p = 0; p < 6; p++)
                ffma2(x2[p], hp, cw.pW2[f * 6 + p]);
        }
        #pragma unroll
        for (int p = 0; p < 6; p++) {
            float u, v; unpack2(x2[p], u, v);
            X[2*p] += u; X[2*p+1] += v;
        }
    }

    // ---- hand off final X ----
    {
        float* dst = &sXf[w][lane * D];
        F4(dst)     = make_float4(X[0], X[1], X[2],  X[3]);
        F4(dst + 4) = make_float4(X[4], X[5], X[6],  X[7]);
        F4(dst + 8) = make_float4(X[8], X[9], X[10], X[11]);
    }
    __syncwarp();

    // ---- phase 9: logits = Xf @ embed^T + b_lm ----
    // two column-half passes; per pass 12 packed embT regs; rows software-
    // pipelined in pairs so LDS latency overlaps the FFMA2 chains.
    {
        const float* xf = sXf[w];
        float* obase = out + (size_t)item_base * (N * V);

        #pragma unroll
        for (int pass = 0; pass < 2; pass++) {
            const int v0 = lane * 2 + pass * 64;
            ull e2[D];
            #pragma unroll
            for (int d = 0; d < D; d++) {
                const float2 e = *reinterpret_cast<const float2*>(&sEmbT[d * V + v0]);
                e2[d] = pack2(e.x, e.y);
            }
            const float2 bl = *reinterpret_cast<const float2*>(&sBlm[v0]);
            const ull bl2 = pack2(bl.x, bl.y);

            // prologue: row 0
            float4 xa = F4C(&xf[0]), xb = F4C(&xf[4]), xc = F4C(&xf[8]);

            #pragma unroll 1
            for (int r = 0; r < 4 * N; r += 2) {
                // prefetch row r+1
                float4 ya = F4C(&xf[(r + 1) * D]);
                float4 yb = F4C(&xf[(r + 1) * D + 4]);
                float4 yc = F4C(&xf[(r + 1) * D + 8]);

                // compute row r
                {
                    ull acc = bl2;
                    ffma2(acc, pack2(xa.x, xa.x), e2[0]);
                    ffma2(acc, pack2(xa.y, xa.y), e2[1]);
                    ffma2(acc, pack2(xa.z, xa.z), e2[2]);
                    ffma2(acc, pack2(xa.w, xa.w), e2[3]);
                    ffma2(acc, pack2(xb.x, xb.x), e2[4]);
                    ffma2(acc, pack2(xb.y, xb.y), e2[5]);
                    ffma2(acc, pack2(xb.z, xb.z), e2[6]);
                    ffma2(acc, pack2(xb.w, xb.w), e2[7]);
                    ffma2(acc, pack2(xc.x, xc.x), e2[8]);
                    ffma2(acc, pack2(xc.y, xc.y), e2[9]);
                    ffma2(acc, pack2(xc.z, xc.z), e2[10]);
                    ffma2(acc, pack2(xc.w, xc.w), e2[11]);
                    float u, v; unpack2(acc, u, v);
                    *reinterpret_cast<float2*>(&obase[(size_t)r * V + v0]) =
                        make_float2(u, v);
                }

                // prefetch row r+2 (over-reads into padding on the last iter)
                xa = F4C(&xf[(r + 2) * D]);
                xb = F4C(&xf[(r + 2) * D + 4]);
                xc = F4C(&xf[(r + 2) * D + 8]);

                // compute row r+1
                {
                    ull acc = bl2;
                    ffma2(acc, pack2(ya.x, ya.x), e2[0]);
                    ffma2(acc, pack2(ya.y, ya.y), e2[1]);
                    ffma2(acc, pack2(ya.z, ya.z), e2[2]);
                    ffma2(acc, pack2(ya.w, ya.w), e2[3]);
                    ffma2(acc, pack2(yb.x, yb.x), e2[4]);
                    ffma2(acc, pack2(yb.y, yb.y), e2[5]);
                    ffma2(acc, pack2(yb.z, yb.z), e2[6]);
                    ffma2(acc, pack2(yb.w, yb.w), e2[7]);
                    ffma2(acc, pack2(yc.x, yc.x), e2[8]);
                    ffma2(acc, pack2(yc.y, yc.y), e2[9]);
                    ffma2(acc, pack2(yc.z, yc.z), e2[10]);
                    ffma2(acc, pack2(yc.w, yc.w), e2[11]);
                    float u, v; unpack2(acc, u, v);
                    *reinterpret_cast<float2*>(&obase[(size_t)(r + 1) * V + v0]) =
                        make_float2(u, v);
                }
            }
        }
    }
}

}  // namespace

extern "C" void kernel_launch(void* const* d_in, const int* in_sizes, int n_in,
                              void* d_out, int out_size)
{
    const int*   x     = (const int*)  d_in[0];
    const float* embed = (const float*)d_in[1];
    const float* pos   = (const float*)d_in[2];
    const float* blm   = (const float*)d_in[15];
    float* out = (float*)d_out;

    // 1) gather + pair-pack all weights into staging (one kernel node)
    pack_weights_kernel<<<1, 256>>>(
        (const float*)d_in[3],  (const float*)d_in[4],
        (const float*)d_in[5],  (const float*)d_in[6],
        (const float*)d_in[7],  (const float*)d_in[8],
        (const float*)d_in[9],  (const float*)d_in[10],
        (const float*)d_in[11], (const float*)d_in[12],
        (const float*)d_in[13], (const float*)d_in[14]);

    // 2) one D2D copy staging -> constant bank (one memcpy node)
    void *dstC, *srcG;
    cudaGetSymbolAddress(&dstC, cw);
    cudaGetSymbolAddress(&srcG, gStage);
    cudaMemcpyAsync(dstC, srcG, sizeof(ConstW), cudaMemcpyDeviceToDevice);

    // 3) main kernel
    const int batch  = in_sizes[0] / N;              // 32768
    const int blocks = batch / ITEMS_PER_BLOCK;      // 1024

    tiny_transformer_kernel<<<blocks, THREADS>>>(x, embed, pos, blm, out);
}